// round 2
// baseline (speedup 1.0000x reference)
#include <cuda_runtime.h>
#include <cuda_bf16.h>
#include <cstdint>

#define NN 10000
#define DD 32

// ---------------- device scratch (no allocation allowed) ----------------
__device__ float g_XW1[NN * 1024];   // node_feats @ Wih1^T ; later unused
__device__ float g_gates[NN * 1024]; // per-step gates; later XW2
__device__ float g_h1[NN * 256];
__device__ float g_c1[NN * 256];
__device__ float g_hs[NN * 256];

// ---------------- helpers ----------------
__device__ __forceinline__ unsigned long long pack2f(float x) {
    unsigned long long r;
    asm("mov.b64 %0, {%1, %1};" : "=l"(r) : "f"(x));
    return r;
}
__device__ __forceinline__ float2 unpack2f(unsigned long long v) {
    float2 r;
    asm("mov.b64 {%0, %1}, %2;" : "=f"(r.x), "=f"(r.y) : "l"(v));
    return r;
}
#define FMA2(acc, a, b) asm("fma.rn.f32x2 %0, %1, %2, %0;" : "+l"(acc) : "l"(a), "l"(b))

__device__ __forceinline__ float sigm(float x)   { return 1.f / (1.f + __expf(-x)); }
__device__ __forceinline__ float tanh_f(float x) { return 1.f - 2.f / (__expf(2.f * x) + 1.f); }

__device__ __forceinline__ uint32_t smem_u32(const void* p) {
    uint32_t a;
    asm("{ .reg .u64 t; cvta.to.shared.u64 t, %1; cvt.u32.u64 %0, t; }" : "=r"(a) : "l"(p));
    return a;
}
__device__ __forceinline__ uint32_t ctarank() {
    uint32_t r; asm("mov.u32 %0, %%cluster_ctarank;" : "=r"(r)); return r;
}

// ---------------- generic K=256 GEMM: C = A @ W^T (+b1+b2) (+ew*gXW[edge]) ----------------
#define LOAD_AB(off) do { \
    if (aval) { ra0 = *(const float4*)(Arow + (off)); ra1 = *(const float4*)(Arow + (off) + 4); } \
    else      { ra0 = zf4; ra1 = zf4; } \
    rb0 = *(const float4*)(Wrow + (off)); rb1 = *(const float4*)(Wrow + (off) + 4); \
} while (0)

#define STORE_AB(buf) do { \
    As[buf][lc+0][lr]=ra0.x; As[buf][lc+1][lr]=ra0.y; As[buf][lc+2][lr]=ra0.z; As[buf][lc+3][lr]=ra0.w; \
    As[buf][lc+4][lr]=ra1.x; As[buf][lc+5][lr]=ra1.y; As[buf][lc+6][lr]=ra1.z; As[buf][lc+7][lr]=ra1.w; \
    Bs[buf][lc+0][lr]=rb0.x; Bs[buf][lc+1][lr]=rb0.y; Bs[buf][lc+2][lr]=rb0.z; Bs[buf][lc+3][lr]=rb0.w; \
    Bs[buf][lc+4][lr]=rb1.x; Bs[buf][lc+5][lr]=rb1.y; Bs[buf][lc+6][lr]=rb1.z; Bs[buf][lc+7][lr]=rb1.w; \
} while (0)

__global__ __launch_bounds__(256, 2) void gemm256_kernel(
    const float* __restrict__ A, const float* __restrict__ W,
    float* __restrict__ C, int M, int Nout,
    const float* __restrict__ b1, const float* __restrict__ b2,
    const float* __restrict__ gXW, const int* __restrict__ edges,
    const float* __restrict__ ew, int t)
{
    __shared__ __align__(16) float As[2][16][128];
    __shared__ __align__(16) float Bs[2][16][128];
    __shared__ int   sIdx[128];
    __shared__ float sWt[128];

    int tid = threadIdx.x;
    int rowBase = blockIdx.y * 128;
    int colBase = blockIdx.x * 128;

    if (gXW != nullptr && tid < 128) {
        int r = rowBase + tid;
        if (r < M) { sIdx[tid] = edges[r * DD + t]; sWt[tid] = ew[r * DD + t]; }
    }

    int lr = tid >> 1;
    int lc = (tid & 1) * 8;
    int ar = rowBase + lr;
    const float* Arow = A + (size_t)ar * 256 + lc;
    const float* Wrow = W + (size_t)(colBase + lr) * 256 + lc;
    bool aval = (ar < M);
    float4 zf4 = make_float4(0.f, 0.f, 0.f, 0.f);

    int tm = (tid >> 4) * 8;
    int tn = (tid & 15) * 8;

    unsigned long long acc[8][4];
    #pragma unroll
    for (int i = 0; i < 8; i++)
        #pragma unroll
        for (int j = 0; j < 4; j++) acc[i][j] = 0ull;

    float4 ra0, ra1, rb0, rb1;
    LOAD_AB(0);
    STORE_AB(0);
    __syncthreads();

    #pragma unroll 1
    for (int kt = 0; kt < 16; kt++) {
        int buf = kt & 1;
        if (kt < 15) LOAD_AB((kt + 1) * 16);
        #pragma unroll
        for (int kk = 0; kk < 16; kk++) {
            float4 a0 = *(const float4*)&As[buf][kk][tm];
            float4 a1 = *(const float4*)&As[buf][kk][tm + 4];
            ulonglong2 bq0 = *(const ulonglong2*)&Bs[buf][kk][tn];
            ulonglong2 bq1 = *(const ulonglong2*)&Bs[buf][kk][tn + 4];
            float av[8] = {a0.x, a0.y, a0.z, a0.w, a1.x, a1.y, a1.z, a1.w};
            #pragma unroll
            for (int i = 0; i < 8; i++) {
                unsigned long long aa = pack2f(av[i]);
                FMA2(acc[i][0], aa, bq0.x);
                FMA2(acc[i][1], aa, bq0.y);
                FMA2(acc[i][2], aa, bq1.x);
                FMA2(acc[i][3], aa, bq1.y);
            }
        }
        if (kt < 15) STORE_AB(buf ^ 1);
        __syncthreads();
    }

    float bc[8];
    #pragma unroll
    for (int j = 0; j < 8; j++) {
        int cidx = colBase + tn + j;
        float b = (b1 != nullptr) ? b1[cidx] : 0.f;
        if (b2 != nullptr) b += b2[cidx];
        bc[j] = b;
    }
    #pragma unroll
    for (int i = 0; i < 8; i++) {
        int r = rowBase + tm + i;
        if (r < M) {
            float2 v0 = unpack2f(acc[i][0]);
            float2 v1 = unpack2f(acc[i][1]);
            float2 v2 = unpack2f(acc[i][2]);
            float2 v3 = unpack2f(acc[i][3]);
            float o[8] = {v0.x + bc[0], v0.y + bc[1], v1.x + bc[2], v1.y + bc[3],
                          v2.x + bc[4], v2.y + bc[5], v3.x + bc[6], v3.y + bc[7]};
            if (gXW != nullptr) {
                const float* gp = gXW + (size_t)sIdx[tm + i] * 1024 + colBase + tn;
                float w = sWt[tm + i];
                float4 g0 = *(const float4*)gp;
                float4 g1 = *(const float4*)(gp + 4);
                o[0] += w * g0.x; o[1] += w * g0.y; o[2] += w * g0.z; o[3] += w * g0.w;
                o[4] += w * g1.x; o[5] += w * g1.y; o[6] += w * g1.z; o[7] += w * g1.w;
            }
            float* cp = C + (size_t)r * Nout + colBase + tn;
            *(float4*)cp       = make_float4(o[0], o[1], o[2], o[3]);
            *(float4*)(cp + 4) = make_float4(o[4], o[5], o[6], o[7]);
        }
    }
}

// ---------------- LSTM1 first step (h=c=0): gates = b + ew*XW1[edge] ----------------
__global__ void step0_kernel(const float* __restrict__ XW1, const int* __restrict__ edges,
                             const float* __restrict__ ew,
                             const float* __restrict__ bih1, const float* __restrict__ bhh1,
                             float* __restrict__ h, float* __restrict__ c)
{
    int idx = blockIdx.x * blockDim.x + threadIdx.x;
    if (idx >= NN * 256) return;
    int n = idx >> 8, j = idx & 255;
    int e = edges[n * DD];
    float w = ew[n * DD];
    const float* x = XW1 + (size_t)e * 1024 + j;
    float ig = bih1[j]       + bhh1[j]       + w * x[0];
    float gg = bih1[512 + j] + bhh1[512 + j] + w * x[512];
    float og = bih1[768 + j] + bhh1[768 + j] + w * x[768];
    float cc = sigm(ig) * tanh_f(gg);
    h[idx] = sigm(og) * tanh_f(cc);
    c[idx] = cc;
}

// ---------------- LSTM1 cell update ----------------
__global__ void lstm1_cell_kernel(const float* __restrict__ gates,
                                  float* __restrict__ h, float* __restrict__ c)
{
    int idx = blockIdx.x * blockDim.x + threadIdx.x;
    if (idx >= NN * 256) return;
    int n = idx >> 8, j = idx & 255;
    const float* g = gates + (size_t)n * 1024 + j;
    float ig = g[0], fg = g[256], gg = g[512], og = g[768];
    float cc = c[idx];
    cc = sigm(fg) * cc + sigm(ig) * tanh_f(gg);
    h[idx] = sigm(og) * tanh_f(cc);
    c[idx] = cc;
}

// ---------------- LSTM2: sequential over N nodes on an 8-CTA cluster ----------------
#define CL 8
__global__ void __cluster_dims__(CL, 1, 1) __launch_bounds__(256, 1)
lstm2_kernel(const float* __restrict__ xw2,   // [NN,1024], includes biases
             const float* __restrict__ Whh2,  // [1024,256]
             float* __restrict__ hs)          // [NN,256]
{
    __shared__ __align__(16) float h_buf[2][256];
    __shared__ float sg[128];
    __shared__ float sh[32];
    __shared__ float sx[2][128];

    int tid = threadIdx.x;
    int rank = (int)ctarank();
    int lcol = tid >> 1;          // 0..127: local column
    int khalf = tid & 1;          // K half 0/1
    int q = lcol >> 5, ul = lcol & 31;
    int gcol = q * 256 + rank * 32 + ul;

    // per-thread weights: Whh2[gcol][khalf*128 .. +128)
    ulonglong2 wreg[32];
    {
        const ulonglong2* wp = (const ulonglong2*)(Whh2 + (size_t)gcol * 256 + khalf * 128);
        #pragma unroll
        for (int i = 0; i < 32; i++) wreg[i] = wp[i];
    }

    h_buf[0][tid] = 0.f;
    if (tid < 128) sx[0][tid] = xw2[(size_t)(tid >> 5) * 256 + rank * 32 + (tid & 31)];
    float c_reg = 0.f;
    __syncthreads();
    asm volatile("barrier.cluster.arrive.aligned;" ::: "memory");
    asm volatile("barrier.cluster.wait.aligned;" ::: "memory");

    for (int n = 0; n < NN; n++) {
        int p = n & 1;
        // prefetch next step's xw2 slice (hidden under the matvec)
        float xnext = 0.f;
        if (n < NN - 1 && tid < 128)
            xnext = xw2[(size_t)(n + 1) * 1024 + (tid >> 5) * 256 + rank * 32 + (tid & 31)];

        // matvec: 128 MACs per thread, f32x2, 2 accumulators
        const ulonglong2* hp = (const ulonglong2*)(&h_buf[p][khalf * 128]);
        unsigned long long acc0 = pack2f(0.f), acc1 = pack2f(0.f);
        #pragma unroll
        for (int i = 0; i < 32; i += 2) {
            ulonglong2 hv0 = hp[i];
            ulonglong2 hv1 = hp[i + 1];
            FMA2(acc0, hv0.x, wreg[i].x);
            FMA2(acc1, hv0.y, wreg[i].y);
            FMA2(acc0, hv1.x, wreg[i + 1].x);
            FMA2(acc1, hv1.y, wreg[i + 1].y);
        }
        float2 a0 = unpack2f(acc0), a1 = unpack2f(acc1);
        float v = a0.x + a0.y + a1.x + a1.y;
        v += __shfl_xor_sync(0xffffffffu, v, 1);
        if (khalf == 0) sg[lcol] = v;
        if (n < NN - 1 && tid < 128) sx[p ^ 1][tid] = xnext;
        __syncthreads();

        // cell update: thread u (<32) owns hidden unit rank*32+u
        if (tid < 32) {
            int u = tid;
            float ig = sg[u]      + sx[p][u];
            float fg = sg[32 + u] + sx[p][32 + u];
            float gg = sg[64 + u] + sx[p][64 + u];
            float og = sg[96 + u] + sx[p][96 + u];
            c_reg = sigm(fg) * c_reg + sigm(ig) * tanh_f(gg);
            float hn = sigm(og) * tanh_f(c_reg);
            sh[u] = hn;
            hs[(size_t)n * 256 + rank * 32 + u] = hn;
        }
        __syncthreads();

        // broadcast the 32 new h values to every CTA's other h buffer
        {
            int dst = tid >> 5;
            int u = tid & 31;
            float val = sh[u];
            uint32_t laddr = smem_u32(&h_buf[p ^ 1][rank * 32 + u]);
            uint32_t raddr;
            asm("mapa.shared::cluster.u32 %0, %1, %2;" : "=r"(raddr) : "r"(laddr), "r"(dst));
            asm volatile("st.shared::cluster.f32 [%0], %1;" :: "r"(raddr), "f"(val));
        }
        asm volatile("barrier.cluster.arrive.aligned;" ::: "memory");
        asm volatile("barrier.cluster.wait.aligned;" ::: "memory");
    }
}

// ---------------- launch ----------------
extern "C" void kernel_launch(void* const* d_in, const int* in_sizes, int n_in,
                              void* d_out, int out_size)
{
    const float* node_feats = (const float*)d_in[0];
    const int*   edges      = (const int*)d_in[1];
    const float* ew         = (const float*)d_in[2];
    const float* Wih1       = (const float*)d_in[3];
    const float* Whh1       = (const float*)d_in[4];
    const float* bih1       = (const float*)d_in[5];
    const float* bhh1       = (const float*)d_in[6];
    const float* Wih2       = (const float*)d_in[7];
    const float* Whh2       = (const float*)d_in[8];
    const float* bih2       = (const float*)d_in[9];
    const float* bhh2       = (const float*)d_in[10];
    const float* Wl         = (const float*)d_in[11];
    const float* bl         = (const float*)d_in[12];
    const float* bias       = (const float*)d_in[13];
    float* out = (float*)d_out;

    void *pXW1, *pGates, *pH1, *pC1, *pHs;
    cudaGetSymbolAddress(&pXW1,   g_XW1);
    cudaGetSymbolAddress(&pGates, g_gates);
    cudaGetSymbolAddress(&pH1,    g_h1);
    cudaGetSymbolAddress(&pC1,    g_c1);
    cudaGetSymbolAddress(&pHs,    g_hs);
    float* XW1   = (float*)pXW1;
    float* gates = (float*)pGates;
    float* h1    = (float*)pH1;
    float* c1    = (float*)pC1;
    float* hs    = (float*)pHs;

    dim3 blk(256);
    dim3 grid_g(8, 79);   // Nout=1024, M=10000
    int ew_blocks = (NN * 256 + 255) / 256;

    // XW1 = node_feats @ Wih1^T
    gemm256_kernel<<<grid_g, blk>>>(node_feats, Wih1, XW1, NN, 1024,
                                    nullptr, nullptr, nullptr, nullptr, nullptr, 0);
    // t = 0 (h=c=0)
    step0_kernel<<<ew_blocks, blk>>>(XW1, edges, ew, bih1, bhh1, h1, c1);
    // t = 1..31
    for (int t = 1; t < DD; t++) {
        gemm256_kernel<<<grid_g, blk>>>(h1, Whh1, gates, NN, 1024,
                                        bih1, bhh1, XW1, edges, ew, t);
        lstm1_cell_kernel<<<ew_blocks, blk>>>(gates, h1, c1);
    }
    // XW2 = h_agg @ Wih2^T + (bih2+bhh2)   (reuse gates buffer)
    gemm256_kernel<<<grid_g, blk>>>(h1, Wih2, gates, NN, 1024,
                                    bih2, bhh2, nullptr, nullptr, nullptr, 0);
    // sequential LSTM2 on an 8-CTA cluster
    lstm2_kernel<<<CL, blk>>>(gates, Whh2, hs);
    // out = hs @ Wl^T + bl + bias
    dim3 grid_f(2, 79);
    gemm256_kernel<<<grid_f, blk>>>(hs, Wl, out, NN, 256,
                                    bl, bias, nullptr, nullptr, nullptr, 0);
    (void)in_sizes; (void)n_in; (void)out_size;
}

// round 4
// speedup vs baseline: 1.3597x; 1.3597x over previous
#include <cuda_runtime.h>
#include <cuda_bf16.h>
#include <cstdint>

#define NN 10000
#define DD 32
#define CL 8

// ---------------- device scratch (no allocation allowed) ----------------
__device__ float g_XW1[NN * 1024];   // node_feats @ Wih1^T
__device__ float g_gates[NN * 1024]; // per-step gates; later XW2
__device__ float g_h1[NN * 256];
__device__ float g_c1[NN * 256];
__device__ float g_hs[NN * 256];

// ---------------- helpers ----------------
__device__ __forceinline__ unsigned long long pack2f(float x) {
    unsigned long long r;
    asm("mov.b64 %0, {%1, %1};" : "=l"(r) : "f"(x));
    return r;
}
__device__ __forceinline__ float2 unpack2f(unsigned long long v) {
    float2 r;
    asm("mov.b64 {%0, %1}, %2;" : "=f"(r.x), "=f"(r.y) : "l"(v));
    return r;
}
#define FMA2(acc, a, b) asm("fma.rn.f32x2 %0, %1, %2, %0;" : "+l"(acc) : "l"(a), "l"(b))

__device__ __forceinline__ float sigm(float x)   { return 1.f / (1.f + __expf(-x)); }
__device__ __forceinline__ float tanh_f(float x) { return 1.f - 2.f / (__expf(2.f * x) + 1.f); }

__device__ __forceinline__ uint32_t smem_u32(const void* p) {
    uint32_t a;
    asm("{ .reg .u64 t; cvta.to.shared.u64 t, %1; cvt.u32.u64 %0, t; }" : "=r"(a) : "l"(p));
    return a;
}
__device__ __forceinline__ uint32_t ctarank() {
    uint32_t r; asm("mov.u32 %0, %%cluster_ctarank;" : "=r"(r)); return r;
}

#define MBAR_INIT(addr, cnt) \
    asm volatile("mbarrier.init.shared.b64 [%0], %1;" :: "r"((uint32_t)(addr)), "r"((uint32_t)(cnt)) : "memory")

#define MBAR_ARM_TX(addr, tx) \
    asm volatile("mbarrier.arrive.expect_tx.shared.b64 _, [%0], %1;" :: "r"((uint32_t)(addr)), "r"((uint32_t)(tx)) : "memory")

#define MBAR_WAIT_CLUSTER(addr, ph) do {                                              \
    uint32_t _done = 0;                                                               \
    while (!_done) {                                                                  \
        asm volatile("{\n\t.reg .pred p;\n\t"                                         \
            "mbarrier.try_wait.parity.acquire.cluster.shared::cta.b64 p, [%1], %2;\n\t" \
            "selp.b32 %0, 1, 0, p;\n\t}"                                              \
            : "=r"(_done) : "r"((uint32_t)(addr)), "r"((uint32_t)(ph)) : "memory");   \
    }                                                                                 \
} while (0)

#define ST_ASYNC_F32(raddr, bits, rmbar) \
    asm volatile("st.async.weak.shared::cluster.mbarrier::complete_tx::bytes.b32 [%0], %1, [%2];" \
                 :: "r"(raddr), "r"(bits), "r"(rmbar) : "memory")

// ---------------- generic K=256 GEMM: C = A @ W^T (+b1+b2) (+ew*gXW[edge]) ----------------
#define LOAD_AB(off) do { \
    if (aval) { ra0 = *(const float4*)(Arow + (off)); ra1 = *(const float4*)(Arow + (off) + 4); } \
    else      { ra0 = zf4; ra1 = zf4; } \
    rb0 = *(const float4*)(Wrow + (off)); rb1 = *(const float4*)(Wrow + (off) + 4); \
} while (0)

#define STORE_AB(buf) do { \
    As[buf][lc+0][lr]=ra0.x; As[buf][lc+1][lr]=ra0.y; As[buf][lc+2][lr]=ra0.z; As[buf][lc+3][lr]=ra0.w; \
    As[buf][lc+4][lr]=ra1.x; As[buf][lc+5][lr]=ra1.y; As[buf][lc+6][lr]=ra1.z; As[buf][lc+7][lr]=ra1.w; \
    Bs[buf][lc+0][lr]=rb0.x; Bs[buf][lc+1][lr]=rb0.y; Bs[buf][lc+2][lr]=rb0.z; Bs[buf][lc+3][lr]=rb0.w; \
    Bs[buf][lc+4][lr]=rb1.x; Bs[buf][lc+5][lr]=rb1.y; Bs[buf][lc+6][lr]=rb1.z; Bs[buf][lc+7][lr]=rb1.w; \
} while (0)

__global__ __launch_bounds__(256, 2) void gemm256_kernel(
    const float* __restrict__ A, const float* __restrict__ W,
    float* __restrict__ C, int M, int Nout,
    const float* __restrict__ b1, const float* __restrict__ b2,
    const float* __restrict__ gXW, const int* __restrict__ edges,
    const float* __restrict__ ew, int t)
{
    __shared__ __align__(16) float As[2][16][128];
    __shared__ __align__(16) float Bs[2][16][128];
    __shared__ int   sIdx[128];
    __shared__ float sWt[128];

    int tid = threadIdx.x;
    int rowBase = blockIdx.y * 128;
    int colBase = blockIdx.x * 128;

    if (gXW != nullptr && tid < 128) {
        int r = rowBase + tid;
        if (r < M) { sIdx[tid] = edges[r * DD + t]; sWt[tid] = ew[r * DD + t]; }
    }

    int lr = tid >> 1;
    int lc = (tid & 1) * 8;
    int ar = rowBase + lr;
    const float* Arow = A + (size_t)ar * 256 + lc;
    const float* Wrow = W + (size_t)(colBase + lr) * 256 + lc;
    bool aval = (ar < M);
    float4 zf4 = make_float4(0.f, 0.f, 0.f, 0.f);

    int tm = (tid >> 4) * 8;
    int tn = (tid & 15) * 8;

    unsigned long long acc[8][4];
    #pragma unroll
    for (int i = 0; i < 8; i++)
        #pragma unroll
        for (int j = 0; j < 4; j++) acc[i][j] = 0ull;

    float4 ra0, ra1, rb0, rb1;
    LOAD_AB(0);
    STORE_AB(0);
    __syncthreads();

    #pragma unroll 1
    for (int kt = 0; kt < 16; kt++) {
        int buf = kt & 1;
        if (kt < 15) LOAD_AB((kt + 1) * 16);
        #pragma unroll
        for (int kk = 0; kk < 16; kk++) {
            float4 a0 = *(const float4*)&As[buf][kk][tm];
            float4 a1 = *(const float4*)&As[buf][kk][tm + 4];
            ulonglong2 bq0 = *(const ulonglong2*)&Bs[buf][kk][tn];
            ulonglong2 bq1 = *(const ulonglong2*)&Bs[buf][kk][tn + 4];
            float av[8] = {a0.x, a0.y, a0.z, a0.w, a1.x, a1.y, a1.z, a1.w};
            #pragma unroll
            for (int i = 0; i < 8; i++) {
                unsigned long long aa = pack2f(av[i]);
                FMA2(acc[i][0], aa, bq0.x);
                FMA2(acc[i][1], aa, bq0.y);
                FMA2(acc[i][2], aa, bq1.x);
                FMA2(acc[i][3], aa, bq1.y);
            }
        }
        if (kt < 15) STORE_AB(buf ^ 1);
        __syncthreads();
    }

    float bc[8];
    #pragma unroll
    for (int j = 0; j < 8; j++) {
        int cidx = colBase + tn + j;
        float b = (b1 != nullptr) ? b1[cidx] : 0.f;
        if (b2 != nullptr) b += b2[cidx];
        bc[j] = b;
    }
    #pragma unroll
    for (int i = 0; i < 8; i++) {
        int r = rowBase + tm + i;
        if (r < M) {
            float2 v0 = unpack2f(acc[i][0]);
            float2 v1 = unpack2f(acc[i][1]);
            float2 v2 = unpack2f(acc[i][2]);
            float2 v3 = unpack2f(acc[i][3]);
            float o[8] = {v0.x + bc[0], v0.y + bc[1], v1.x + bc[2], v1.y + bc[3],
                          v2.x + bc[4], v2.y + bc[5], v3.x + bc[6], v3.y + bc[7]};
            if (gXW != nullptr) {
                const float* gp = gXW + (size_t)sIdx[tm + i] * 1024 + colBase + tn;
                float w = sWt[tm + i];
                float4 g0 = *(const float4*)gp;
                float4 g1 = *(const float4*)(gp + 4);
                o[0] += w * g0.x; o[1] += w * g0.y; o[2] += w * g0.z; o[3] += w * g0.w;
                o[4] += w * g1.x; o[5] += w * g1.y; o[6] += w * g1.z; o[7] += w * g1.w;
            }
            float* cp = C + (size_t)r * Nout + colBase + tn;
            *(float4*)cp       = make_float4(o[0], o[1], o[2], o[3]);
            *(float4*)(cp + 4) = make_float4(o[4], o[5], o[6], o[7]);
        }
    }
}

// ---------------- LSTM1 first step (h=c=0): gates = b + ew*XW1[edge] ----------------
__global__ void step0_kernel(const float* __restrict__ XW1, const int* __restrict__ edges,
                             const float* __restrict__ ew,
                             const float* __restrict__ bih1, const float* __restrict__ bhh1,
                             float* __restrict__ h, float* __restrict__ c)
{
    int idx = blockIdx.x * blockDim.x + threadIdx.x;
    if (idx >= NN * 256) return;
    int n = idx >> 8, j = idx & 255;
    int e = edges[n * DD];
    float w = ew[n * DD];
    const float* x = XW1 + (size_t)e * 1024 + j;
    float ig = bih1[j]       + bhh1[j]       + w * x[0];
    float gg = bih1[512 + j] + bhh1[512 + j] + w * x[512];
    float og = bih1[768 + j] + bhh1[768 + j] + w * x[768];
    float cc = sigm(ig) * tanh_f(gg);
    h[idx] = sigm(og) * tanh_f(cc);
    c[idx] = cc;
}

// ---------------- LSTM1 cell update ----------------
__global__ void lstm1_cell_kernel(const float* __restrict__ gates,
                                  float* __restrict__ h, float* __restrict__ c)
{
    int idx = blockIdx.x * blockDim.x + threadIdx.x;
    if (idx >= NN * 256) return;
    int n = idx >> 8, j = idx & 255;
    const float* g = gates + (size_t)n * 1024 + j;
    float ig = g[0], fg = g[256], gg = g[512], og = g[768];
    float cc = c[idx];
    cc = sigm(fg) * cc + sigm(ig) * tanh_f(gg);
    h[idx] = sigm(og) * tanh_f(cc);
    c[idx] = cc;
}

// ---------------- LSTM2: sequential over N nodes on an 8-CTA cluster ----------------
// Per CTA (rank r): computes the 128 gate-columns for units [32r, 32r+32).
// Thread (w = warp, l = lane): half = l>>4, sl = l&15.
//   cols:   lc0 = 16*w + 8*half  .. +8   (8 columns)
//   k-set:  {64*j + 4*sl + 0..3  for j in 0..3}  (16 of 256 h values, conflict-free LDS.128)
// h broadcast to all CTAs via st.async + mbarrier (1024 B tx per step).
__global__ void __cluster_dims__(CL, 1, 1) __launch_bounds__(256, 1)
lstm2_kernel(const float* __restrict__ xw2,   // [NN,1024], biases included
             const float* __restrict__ Whh2,  // [1024,256]
             float* __restrict__ hs)          // [NN,256]
{
    __shared__ __align__(16) float h_buf[2][256];
    __shared__ __align__(16) float sg[128];
    __shared__ __align__(8)  unsigned long long mbar[2];

    int tid = threadIdx.x;
    int w = tid >> 5, l = tid & 31;
    int half = l >> 4, sl = l & 15;
    int rank = (int)ctarank();
    int lc0 = w * 16 + half * 8;

    // per-thread weights: wp[c][2j], wp[c][2j+1] = Whh2[gcol(lc0+c)][64j+4sl .. +4]
    unsigned long long wp[8][8];
    #pragma unroll
    for (int c = 0; c < 8; c++) {
        int lc = lc0 + c;
        int gcol = (lc >> 5) * 256 + rank * 32 + (lc & 31);
        const float* wr = Whh2 + (size_t)gcol * 256;
        #pragma unroll
        for (int j = 0; j < 4; j++) {
            ulonglong2 tq = *(const ulonglong2*)(wr + j * 64 + sl * 4);
            wp[c][2 * j]     = tq.x;
            wp[c][2 * j + 1] = tq.y;
        }
    }

    uint32_t hb = smem_u32(&h_buf[0][0]);
    uint32_t mb = smem_u32(&mbar[0]);
    uint32_t rH[8], rM[8];
    #pragma unroll
    for (int d = 0; d < 8; d++) {
        asm("mapa.shared::cluster.u32 %0, %1, %2;" : "=r"(rH[d]) : "r"(hb), "r"(d));
        asm("mapa.shared::cluster.u32 %0, %1, %2;" : "=r"(rM[d]) : "r"(mb), "r"(d));
    }

    h_buf[0][tid] = 0.f;
    if (tid == 0) {
        MBAR_INIT(mb, 1);
        MBAR_INIT(mb + 8, 1);
        MBAR_ARM_TX(mb + 8, 1024);   // pre-arm slot 1 for h_0
    }
    float c_reg = 0.f;
    float xc[4] = {0.f, 0.f, 0.f, 0.f};
    if (tid < 32) {
        #pragma unroll
        for (int q = 0; q < 4; q++) xc[q] = xw2[q * 256 + rank * 32 + tid];
    }
    __syncthreads();
    asm volatile("barrier.cluster.arrive.aligned;" ::: "memory");
    asm volatile("barrier.cluster.wait.aligned;" ::: "memory");

    int p = 0;
    for (int n = 0; n < NN; n++) {
        // prefetch next step's x for the cell threads
        float xnx[4] = {0.f, 0.f, 0.f, 0.f};
        if (tid < 32 && n + 1 < NN) {
            const float* xp = xw2 + (size_t)(n + 1) * 1024 + rank * 32 + tid;
            #pragma unroll
            for (int q = 0; q < 4; q++) xnx[q] = xp[q * 256];
        }

        // matvec: 8 cols x 16 k per thread, h loads conflict-free + register reuse x8
        const float* hp = &h_buf[p][0];
        unsigned long long acc[8];
        #pragma unroll
        for (int c = 0; c < 8; c++) acc[c] = 0ull;
        #pragma unroll
        for (int j = 0; j < 4; j++) {
            ulonglong2 hv = *(const ulonglong2*)(hp + j * 64 + sl * 4);
            #pragma unroll
            for (int c = 0; c < 8; c++) {
                FMA2(acc[c], hv.x, wp[c][2 * j]);
                FMA2(acc[c], hv.y, wp[c][2 * j + 1]);
            }
        }
        float v[8];
        #pragma unroll
        for (int c = 0; c < 8; c++) { float2 tv = unpack2f(acc[c]); v[c] = tv.x + tv.y; }
        #pragma unroll
        for (int m = 1; m < 16; m <<= 1)
            #pragma unroll
            for (int c = 0; c < 8; c++)
                v[c] += __shfl_xor_sync(0xffffffffu, v[c], m);
        if (sl == 0) {
            *(float4*)&sg[lc0]     = make_float4(v[0], v[1], v[2], v[3]);
            *(float4*)&sg[lc0 + 4] = make_float4(v[4], v[5], v[6], v[7]);
        }
        // arm slot p for h_{n+1}; placed before the barrier so every peer's
        // complete_tx (which requires our h_n stores, issued after the barrier)
        // is ordered after this arm.
        if (tid == 0) MBAR_ARM_TX(mb + (uint32_t)p * 8, 1024);
        __syncthreads();

        if (tid < 32) {
            float ig = sg[tid]       + xc[0];
            float fg = sg[32 + tid]  + xc[1];
            float gg = sg[64 + tid]  + xc[2];
            float og = sg[96 + tid]  + xc[3];
            c_reg = sigm(fg) * c_reg + sigm(ig) * tanh_f(gg);
            float hn = sigm(og) * tanh_f(c_reg);
            hs[(size_t)n * 256 + rank * 32 + tid] = hn;
            if (n + 1 < NN) {
                uint32_t voff  = (uint32_t)((p ^ 1) * 256 + rank * 32 + tid) * 4u;
                uint32_t mboff = (uint32_t)(p ^ 1) * 8u;
                uint32_t bits  = __float_as_uint(hn);
                #pragma unroll
                for (int d = 0; d < 8; d++)
                    ST_ASYNC_F32(rH[d] + voff, bits, rM[d] + mboff);
            }
            xc[0] = xnx[0]; xc[1] = xnx[1]; xc[2] = xnx[2]; xc[3] = xnx[3];
        }

        if (n + 1 < NN) {
            uint32_t ph = (uint32_t)((n >> 1) & 1);
            MBAR_WAIT_CLUSTER(mb + (uint32_t)(p ^ 1) * 8, ph);
        }
        p ^= 1;
    }
}

// ---------------- launch ----------------
extern "C" void kernel_launch(void* const* d_in, const int* in_sizes, int n_in,
                              void* d_out, int out_size)
{
    const float* node_feats = (const float*)d_in[0];
    const int*   edges      = (const int*)d_in[1];
    const float* ew         = (const float*)d_in[2];
    const float* Wih1       = (const float*)d_in[3];
    const float* Whh1       = (const float*)d_in[4];
    const float* bih1       = (const float*)d_in[5];
    const float* bhh1       = (const float*)d_in[6];
    const float* Wih2       = (const float*)d_in[7];
    const float* Whh2       = (const float*)d_in[8];
    const float* bih2       = (const float*)d_in[9];
    const float* bhh2       = (const float*)d_in[10];
    const float* Wl         = (const float*)d_in[11];
    const float* bl         = (const float*)d_in[12];
    const float* bias       = (const float*)d_in[13];
    float* out = (float*)d_out;

    void *pXW1, *pGates, *pH1, *pC1, *pHs;
    cudaGetSymbolAddress(&pXW1,   g_XW1);
    cudaGetSymbolAddress(&pGates, g_gates);
    cudaGetSymbolAddress(&pH1,    g_h1);
    cudaGetSymbolAddress(&pC1,    g_c1);
    cudaGetSymbolAddress(&pHs,    g_hs);
    float* XW1   = (float*)pXW1;
    float* gates = (float*)pGates;
    float* h1    = (float*)pH1;
    float* c1    = (float*)pC1;
    float* hs    = (float*)pHs;

    dim3 blk(256);
    dim3 grid_g(8, 79);
    int ew_blocks = (NN * 256 + 255) / 256;

    // XW1 = node_feats @ Wih1^T
    gemm256_kernel<<<grid_g, blk>>>(node_feats, Wih1, XW1, NN, 1024,
                                    nullptr, nullptr, nullptr, nullptr, nullptr, 0);
    // t = 0 (h=c=0)
    step0_kernel<<<ew_blocks, blk>>>(XW1, edges, ew, bih1, bhh1, h1, c1);
    // t = 1..31
    for (int t = 1; t < DD; t++) {
        gemm256_kernel<<<grid_g, blk>>>(h1, Whh1, gates, NN, 1024,
                                        bih1, bhh1, XW1, edges, ew, t);
        lstm1_cell_kernel<<<ew_blocks, blk>>>(gates, h1, c1);
    }
    // XW2 = h_agg @ Wih2^T + (bih2+bhh2)
    gemm256_kernel<<<grid_g, blk>>>(h1, Wih2, gates, NN, 1024,
                                    bih2, bhh2, nullptr, nullptr, nullptr, 0);
    // sequential LSTM2 on an 8-CTA cluster
    lstm2_kernel<<<CL, blk>>>(gates, Whh2, hs);
    // out = hs @ Wl^T + bl + bias
    dim3 grid_f(2, 79);
    gemm256_kernel<<<grid_f, blk>>>(hs, Wl, out, NN, 256,
                                    bl, bias, nullptr, nullptr, nullptr, 0);
    (void)in_sizes; (void)n_in; (void)out_size;
}